// round 15
// baseline (speedup 1.0000x reference)
#include <cuda_runtime.h>
#include <cuda_fp16.h>
#include <math.h>
#include <stdint.h>

#define NMAX 50000
#define EMAX 800000
#define DH   256
#define DIN  128
#define NG   64

// ---------------- device scratch ----------------
__device__ __half g_hA[(size_t)NMAX * DH];   // activations ping
__device__ __half g_hB[(size_t)NMAX * DH];   // activations pong
__device__ __half g_x16[(size_t)NMAX * DIN]; // x in fp16
__device__ __half g_agg16[(size_t)NMAX * DH];
// transposed weights fp16: Bt[n][k2], k2 = [rel | root]
__device__ __half g_Bt1[DH * 2 * DIN];
__device__ __half g_Bt2[DH * 2 * DH];

__device__ int   g_rowptr[NMAX + 1];
__device__ int   g_cnt [NMAX];
__device__ int   g_cnt2[NMAX];
__device__ int   g_col [EMAX];
__device__ float g_colsum[DIN];
__device__ float g_ginv[NG];    // 1 / max(graph count, 1)

// ---------------- helpers ----------------
#define MMA(c, a, b) \
    asm volatile("mma.sync.aligned.m16n8k16.row.col.f32.f16.f16.f32 " \
                 "{%0,%1,%2,%3},{%4,%5,%6,%7},{%8,%9},{%0,%1,%2,%3};" \
                 : "+f"((c)[0]), "+f"((c)[1]), "+f"((c)[2]), "+f"((c)[3]) \
                 : "r"((a)[0]), "r"((a)[1]), "r"((a)[2]), "r"((a)[3]), \
                   "r"((b)[0]), "r"((b)[1]))

__device__ __forceinline__ void ldsm4(unsigned* r, const __half* p) {
    unsigned a = (unsigned)__cvta_generic_to_shared((void*)p);
    asm volatile("ldmatrix.sync.aligned.m8n8.x4.shared.b16 {%0,%1,%2,%3}, [%4];"
                 : "=r"(r[0]), "=r"(r[1]), "=r"(r[2]), "=r"(r[3]) : "r"(a));
}
__device__ __forceinline__ void cpa16(__half* dst, const __half* src, bool pred) {
    unsigned d = (unsigned)__cvta_generic_to_shared((void*)dst);
    int sz = pred ? 16 : 0;
    asm volatile("cp.async.cg.shared.global [%0], [%1], 16, %2;"
                 :: "r"(d), "l"(src), "r"(sz));
}
#define CP_COMMIT() asm volatile("cp.async.commit_group;")

// PDL: signal dependents may launch / wait for predecessor grid completion.
__device__ __forceinline__ void gdc_launch() {
    asm volatile("griddepcontrol.launch_dependents;");
}
__device__ __forceinline__ void gdc_wait() {
    asm volatile("griddepcontrol.wait;" ::: "memory");
}

// ---------------- fused front-end: hist | weight prep | x prep ----------------
__global__ void k_front(const int* __restrict__ dst, int E, int n,
                        const float* __restrict__ W1_rel, const float* __restrict__ W1_root,
                        const float* __restrict__ W2_rel, const float* __restrict__ W2_root,
                        const float* __restrict__ x,
                        int HB, int PB, int XB) {
    gdc_launch();
    int bid = blockIdx.x;
    int t = threadIdx.x;
    if (bid < HB) {
        int e = bid * 256 + t;
        if (e < E) atomicAdd(&g_cnt[dst[e]], 1);
    } else if (bid < HB + PB) {
        int i = (bid - HB) * 256 + t;
        const int n1 = DH * 2 * DIN;
        const int n2 = DH * 2 * DH;
        if (i < n1) {
            int nn = i / (2 * DIN), k2 = i % (2 * DIN);
            float w = (k2 < DIN) ? W1_rel[(size_t)k2 * DH + nn]
                                 : W1_root[(size_t)(k2 - DIN) * DH + nn];
            g_Bt1[i] = __float2half_rn(w);
        } else if (i < n1 + n2) {
            int j = i - n1;
            int nn = j / (2 * DH), k2 = j % (2 * DH);
            float w = (k2 < DH) ? W2_rel[(size_t)k2 * DH + nn]
                                : W2_root[(size_t)(k2 - DH) * DH + nn];
            g_Bt2[j] = __float2half_rn(w);
        }
    } else {
        int xb = bid - HB - PB;
        int ch = t & 127;
        int half = t >> 7;
        float acc = 0.f;
        for (int r = xb * 2 + half; r < n; r += XB * 2) {
            float v = x[(size_t)r * DIN + ch];
            acc += v;
            g_x16[(size_t)r * DIN + ch] = __float2half_rn(v);
        }
        atomicAdd(&g_colsum[ch], acc);
    }
}

// ---------------- mid: scan (+cnt2 init) | handcrafted | graph counts ----------------
__global__ void k_mid(int n, float* __restrict__ out, const int* __restrict__ batch) {
    gdc_launch();
    gdc_wait();
    if (blockIdx.x == 0) {
        __shared__ int wsum[32];
        __shared__ int s_carry;
        int t = threadIdx.x, lane = t & 31, w = t >> 5;
        if (t == 0) s_carry = 0;
        __syncthreads();
        int ntile = (n + 1023) >> 10;
        for (int tile = 0; tile < ntile; ++tile) {
            int i = (tile << 10) + t;
            int v = (i < n) ? g_cnt[i] : 0;
            int x = v;
#pragma unroll
            for (int o = 1; o < 32; o <<= 1) {
                int y = __shfl_up_sync(0xFFFFFFFFu, x, o);
                if (lane >= o) x += y;
            }
            if (lane == 31) wsum[w] = x;
            __syncthreads();
            if (w == 0) {
                int s = wsum[lane];
#pragma unroll
                for (int o = 1; o < 32; o <<= 1) {
                    int y = __shfl_up_sync(0xFFFFFFFFu, s, o);
                    if (lane >= o) s += y;
                }
                wsum[lane] = s;
            }
            __syncthreads();
            int warpoff = (w == 0) ? 0 : wsum[w - 1];
            int excl = s_carry + warpoff + x - v;
            if (i < n) { g_rowptr[i] = excl; g_cnt2[i] = excl; }
            int tot = wsum[31];
            __syncthreads();
            if (t == 0) s_carry += tot;
            __syncthreads();
        }
        if (t == 0) g_rowptr[n] = s_carry;
    } else if (blockIdx.x == 1) {
        __shared__ float sh[DIN];
        int t = threadIdx.x;
        float v = (t < DIN) ? g_colsum[t] : 0.f;
        if (t < DIN) sh[t] = v;
        __syncthreads();
        for (int o = 64; o > 0; o >>= 1) {
            if (t < o) sh[t] += sh[t + o];
            __syncthreads();
        }
        float total = sh[0];
        if (t < DIN) out[NG * DH + t] = v / total;
        if (t == 0) out[NG * DH + DIN] = logf(total);
    } else {
        __shared__ int cnt[NG];
        int t = threadIdx.x;
        if (t < NG) cnt[t] = 0;
        __syncthreads();
        for (int i = t; i < n; i += 1024)
            atomicAdd(&cnt[batch[i]], 1);
        __syncthreads();
        if (t < NG) g_ginv[t] = 1.f / fmaxf((float)cnt[t], 1.f);
    }
}

// ---------------- fill: scatter src into CSR slots (cnt2 pre-set to rowptr) ----------------
__global__ void k_fill(const int* __restrict__ src,
                       const int* __restrict__ dst, int E) {
    gdc_launch();
    gdc_wait();
    int e = blockIdx.x * blockDim.x + threadIdx.x;
    if (e < E) {
        int d = dst[e];
        int pos = atomicAdd(&g_cnt2[d], 1);
        g_col[pos] = src[e];
    }
}

// ---------------- aggregation: warp per node, 8-edge unroll (MLP=8) ----------------
// fp16 pairwise-tree accumulate (pairs only — same rounding depth as R13/R14).
// SRC: 0 = g_x16 (D=128), 1 = g_hA (D=256), 2 = g_hB (D=256)
template<int D, int SRC>
__global__ void k_agg16(int n) {
    gdc_launch();
    gdc_wait();
    const __half* __restrict__ h =
        (SRC == 0) ? g_x16 : (SRC == 1 ? (const __half*)g_hA : (const __half*)g_hB);
    int node = blockIdx.x * 8 + (threadIdx.x >> 5);
    int lane = threadIdx.x & 31;
    if (node >= n) return;
    int s = g_rowptr[node];
    int e = g_rowptr[node + 1];

    if (D == 256) {
        float acc[8] = {0, 0, 0, 0, 0, 0, 0, 0};
        int i = s;
#define PACC8(va, vb) { \
        float2 f0 = __half22float2(__hadd2(*(__half2*)&(va).x, *(__half2*)&(vb).x)); \
        float2 f1 = __half22float2(__hadd2(*(__half2*)&(va).y, *(__half2*)&(vb).y)); \
        float2 f2 = __half22float2(__hadd2(*(__half2*)&(va).z, *(__half2*)&(vb).z)); \
        float2 f3 = __half22float2(__hadd2(*(__half2*)&(va).w, *(__half2*)&(vb).w)); \
        acc[0] += f0.x; acc[1] += f0.y; acc[2] += f1.x; acc[3] += f1.y; \
        acc[4] += f2.x; acc[5] += f2.y; acc[6] += f3.x; acc[7] += f3.y; }
        for (; i + 8 <= e; i += 8) {
            int u[8];
#pragma unroll
            for (int j = 0; j < 8; ++j) u[j] = g_col[i + j];
            uint4 v[8];
#pragma unroll
            for (int j = 0; j < 8; ++j)
                v[j] = ((const uint4*)(h + (size_t)u[j] * D))[lane];
            PACC8(v[0], v[1]) PACC8(v[2], v[3])
            PACC8(v[4], v[5]) PACC8(v[6], v[7])
        }
        if (i + 4 <= e) {
            int u0 = g_col[i], u1 = g_col[i + 1], u2 = g_col[i + 2], u3 = g_col[i + 3];
            uint4 v0 = ((const uint4*)(h + (size_t)u0 * D))[lane];
            uint4 v1 = ((const uint4*)(h + (size_t)u1 * D))[lane];
            uint4 v2 = ((const uint4*)(h + (size_t)u2 * D))[lane];
            uint4 v3 = ((const uint4*)(h + (size_t)u3 * D))[lane];
            PACC8(v0, v1) PACC8(v2, v3)
            i += 4;
        }
        if (i + 2 <= e) {
            int u0 = g_col[i], u1 = g_col[i + 1];
            uint4 v0 = ((const uint4*)(h + (size_t)u0 * D))[lane];
            uint4 v1 = ((const uint4*)(h + (size_t)u1 * D))[lane];
            PACC8(v0, v1)
            i += 2;
        }
#undef PACC8
        if (i < e) {
            int u = g_col[i];
            uint4 v = ((const uint4*)(h + (size_t)u * D))[lane];
            float2 f0 = __half22float2(*(__half2*)&v.x);
            float2 f1 = __half22float2(*(__half2*)&v.y);
            float2 f2 = __half22float2(*(__half2*)&v.z);
            float2 f3 = __half22float2(*(__half2*)&v.w);
            acc[0] += f0.x; acc[1] += f0.y; acc[2] += f1.x; acc[3] += f1.y;
            acc[4] += f2.x; acc[5] += f2.y; acc[6] += f3.x; acc[7] += f3.y;
        }
        uint4 o;
        __half2 p0 = __floats2half2_rn(acc[0], acc[1]);
        __half2 p1 = __floats2half2_rn(acc[2], acc[3]);
        __half2 p2 = __floats2half2_rn(acc[4], acc[5]);
        __half2 p3 = __floats2half2_rn(acc[6], acc[7]);
        o.x = *(unsigned*)&p0; o.y = *(unsigned*)&p1;
        o.z = *(unsigned*)&p2; o.w = *(unsigned*)&p3;
        ((uint4*)(g_agg16 + (size_t)node * D))[lane] = o;
    } else {
        float acc[4] = {0, 0, 0, 0};
        int i = s;
#define PACC4(va, vb) { \
        float2 f0 = __half22float2(__hadd2(*(__half2*)&(va).x, *(__half2*)&(vb).x)); \
        float2 f1 = __half22float2(__hadd2(*(__half2*)&(va).y, *(__half2*)&(vb).y)); \
        acc[0] += f0.x; acc[1] += f0.y; acc[2] += f1.x; acc[3] += f1.y; }
        for (; i + 8 <= e; i += 8) {
            int u[8];
#pragma unroll
            for (int j = 0; j < 8; ++j) u[j] = g_col[i + j];
            uint2 v[8];
#pragma unroll
            for (int j = 0; j < 8; ++j)
                v[j] = ((const uint2*)(h + (size_t)u[j] * D))[lane];
            PACC4(v[0], v[1]) PACC4(v[2], v[3])
            PACC4(v[4], v[5]) PACC4(v[6], v[7])
        }
        if (i + 4 <= e) {
            int u0 = g_col[i], u1 = g_col[i + 1], u2 = g_col[i + 2], u3 = g_col[i + 3];
            uint2 v0 = ((const uint2*)(h + (size_t)u0 * D))[lane];
            uint2 v1 = ((const uint2*)(h + (size_t)u1 * D))[lane];
            uint2 v2 = ((const uint2*)(h + (size_t)u2 * D))[lane];
            uint2 v3 = ((const uint2*)(h + (size_t)u3 * D))[lane];
            PACC4(v0, v1) PACC4(v2, v3)
            i += 4;
        }
        if (i + 2 <= e) {
            int u0 = g_col[i], u1 = g_col[i + 1];
            uint2 v0 = ((const uint2*)(h + (size_t)u0 * D))[lane];
            uint2 v1 = ((const uint2*)(h + (size_t)u1 * D))[lane];
            PACC4(v0, v1)
            i += 2;
        }
#undef PACC4
        if (i < e) {
            int u = g_col[i];
            uint2 v = ((const uint2*)(h + (size_t)u * D))[lane];
            float2 f0 = __half22float2(*(__half2*)&v.x);
            float2 f1 = __half22float2(*(__half2*)&v.y);
            acc[0] += f0.x; acc[1] += f0.y; acc[2] += f1.x; acc[3] += f1.y;
        }
        uint2 o;
        __half2 p0 = __floats2half2_rn(acc[0], acc[1]);
        __half2 p1 = __floats2half2_rn(acc[2], acc[3]);
        o.x = *(unsigned*)&p0; o.y = *(unsigned*)&p1;
        ((uint2*)(g_agg16 + (size_t)node * D))[lane] = o;
    }
}

// ---------------- pipelined fp16 tensor-core GEMM ----------------
// h_out = relu([agg16 | root] @ Bt^T + bias), single-product fp16, f32 accum.
// BM=128, BN=128, BK=32, 256 threads, warps 4Mx2N (warp tile 32x64).
// PDL: B-weight prefetch of stages 0/1 issued BEFORE griddepcontrol.wait.
// LAYER 3: no global h write; mean-pool fused into epilogue.
template<int LAYER>
__global__ void __launch_bounds__(256, 2)
k_gemm(const float* __restrict__ bias, int M,
       const int* __restrict__ batch, float* __restrict__ out) {
    constexpr int K  = (LAYER == 1) ? DIN : DH;
    constexpr int K2 = 2 * K;
    constexpr int T  = K2 / 32;
    constexpr bool POOL = (LAYER == 3);

    const __half* __restrict__ root =
        (LAYER == 1) ? g_x16 : (LAYER == 2 ? (const __half*)g_hA : (const __half*)g_hB);
    const __half* __restrict__ Bt = (LAYER == 1) ? g_Bt1 : g_Bt2;
    __half* __restrict__ hout = (LAYER == 2) ? g_hB : g_hA;

    extern __shared__ __half sm[];
    __shared__ float sbias[DH];
    __shared__ int s_batch[128];

    const int tid  = threadIdx.x;
    const int lane = tid & 31;
    const int warp = tid >> 5;
    const int wm   = warp >> 1;
    const int wn   = warp & 1;
    const int gID  = lane >> 2;
    const int tg   = lane & 3;
    const int m0   = blockIdx.x * 128;
    const int n0   = blockIdx.y * 128;

    gdc_launch();

    // ---- independent-of-predecessor prefetch (inputs only) ----
    if (tid < DH) sbias[tid] = bias[tid];
    if (POOL && tid < 128) {
        int r = m0 + tid;
        s_batch[tid] = (r < M) ? batch[r] : -1;
    }

    auto loadB = [&](int it, int s) {
        __half* st = sm + s * 10240;
#pragma unroll
        for (int i = 0; i < 2; ++i) {
            int q = tid + 256 * i;
            int r = q >> 2, cq = q & 3;
            cpa16(st + 5120 + r * 40 + cq * 8,
                  Bt + (size_t)(n0 + r) * K2 + it * 32 + cq * 8, true);
        }
    };
    auto loadA = [&](int it, int s) {
        const bool first = (it * 32 < K);
        const __half* __restrict__ srcA = first ? g_agg16 : root;
        const int col = first ? it * 32 : it * 32 - K;
        __half* st = sm + s * 10240;
#pragma unroll
        for (int i = 0; i < 2; ++i) {
            int q = tid + 256 * i;
            int r = q >> 2, cq = q & 3;
            int gr = m0 + r;
            bool p = gr < M;
            cpa16(st + r * 40 + cq * 8,
                  srcA + (size_t)(p ? gr : 0) * K + col + cq * 8, p);
        }
    };

    loadB(0, 0);
    loadB(1, 1);

    gdc_wait();   // predecessor (agg) complete; A data now valid

    loadA(0, 0);
    CP_COMMIT();   // G0 = {B0, B1, A0}
    loadA(1, 1);
    CP_COMMIT();   // G1 = {A1}

    float c[2][8][4];
#pragma unroll
    for (int mt = 0; mt < 2; ++mt)
#pragma unroll
        for (int nt = 0; nt < 8; ++nt)
#pragma unroll
            for (int q = 0; q < 4; ++q) c[mt][nt][q] = 0.f;

    const int lrow = lane & 15;
    const int lk   = (lane >> 4) * 8;

    for (int it = 0; it < T; ++it) {
        int s = it % 3;
        if (it + 1 < T) asm volatile("cp.async.wait_group 1;");
        else            asm volatile("cp.async.wait_group 0;");
        __syncthreads();
        if (it + 2 < T) { loadA(it + 2, (it + 2) % 3); loadB(it + 2, (it + 2) % 3); }
        CP_COMMIT();

        __half* st = sm + s * 10240;
#pragma unroll
        for (int ks = 0; ks < 32; ks += 16) {
            unsigned a[2][4], b[8][2];
#pragma unroll
            for (int mt = 0; mt < 2; ++mt) {
                int rr = wm * 32 + mt * 16 + lrow;
                ldsm4(a[mt], st + rr * 40 + ks + lk);
            }
#pragma unroll
            for (int nh = 0; nh < 4; ++nh) {
                int nn = wn * 64 + nh * 16 + lrow;
                unsigned r4[4];
                ldsm4(r4, st + 5120 + nn * 40 + ks + lk);
                b[nh * 2][0] = r4[0]; b[nh * 2 + 1][0] = r4[1];
                b[nh * 2][1] = r4[2]; b[nh * 2 + 1][1] = r4[3];
            }
#pragma unroll
            for (int mt = 0; mt < 2; ++mt)
#pragma unroll
                for (int nt = 0; nt < 8; ++nt)
                    MMA(c[mt][nt], a[mt], b[nt]);
        }
    }

    if (!POOL) {
#pragma unroll
        for (int nt = 0; nt < 8; ++nt) {
            int cn = n0 + wn * 64 + nt * 8 + tg * 2;
            float bx = sbias[cn];
            float by = sbias[cn + 1];
#pragma unroll
            for (int mt = 0; mt < 2; ++mt) {
                int r0 = m0 + wm * 32 + mt * 16 + gID;
                int r1 = r0 + 8;
                if (r0 < M) {
                    __half2 o = __floats2half2_rn(fmaxf(c[mt][nt][0] + bx, 0.f),
                                                  fmaxf(c[mt][nt][1] + by, 0.f));
                    *(__half2*)(hout + (size_t)r0 * DH + cn) = o;
                }
                if (r1 < M) {
                    __half2 o = __floats2half2_rn(fmaxf(c[mt][nt][2] + bx, 0.f),
                                                  fmaxf(c[mt][nt][3] + by, 0.f));
                    *(__half2*)(hout + (size_t)r1 * DH + cn) = o;
                }
            }
        }
    } else {
        // bias + relu + fused mean-pool (no global h write)
#pragma unroll
        for (int nt = 0; nt < 8; ++nt) {
            int cn = n0 + wn * 64 + nt * 8 + tg * 2;
            float bx = sbias[cn];
            float by = sbias[cn + 1];
#pragma unroll
            for (int mt = 0; mt < 2; ++mt) {
                int base = wm * 32 + mt * 16;
                int b0 = s_batch[base + gID];
                int b1 = s_batch[base + gID + 8];
                float v00 = fmaxf(c[mt][nt][0] + bx, 0.f);
                float v01 = fmaxf(c[mt][nt][1] + by, 0.f);
                float v10 = fmaxf(c[mt][nt][2] + bx, 0.f);
                float v11 = fmaxf(c[mt][nt][3] + by, 0.f);
                if (b0 < 0) { v00 = 0.f; v01 = 0.f; }
                if (b1 < 0) { v10 = 0.f; v11 = 0.f; }
                int bf = s_batch[base];
                int bl = s_batch[base + 15];
                if (bf == bl) {
                    float s0 = v00 + v10;
                    float s1 = v01 + v11;
                    s0 += __shfl_down_sync(0xFFFFFFFFu, s0, 16);
                    s1 += __shfl_down_sync(0xFFFFFFFFu, s1, 16);
                    s0 += __shfl_down_sync(0xFFFFFFFFu, s0, 8);
                    s1 += __shfl_down_sync(0xFFFFFFFFu, s1, 8);
                    s0 += __shfl_down_sync(0xFFFFFFFFu, s0, 4);
                    s1 += __shfl_down_sync(0xFFFFFFFFu, s1, 4);
                    if (gID == 0 && bf >= 0) {
                        float gi = g_ginv[bf];
                        atomicAdd(&out[(size_t)bf * DH + cn],     s0 * gi);
                        atomicAdd(&out[(size_t)bf * DH + cn + 1], s1 * gi);
                    }
                } else {
                    if (b0 >= 0) {
                        float gi = g_ginv[b0];
                        atomicAdd(&out[(size_t)b0 * DH + cn],     v00 * gi);
                        atomicAdd(&out[(size_t)b0 * DH + cn + 1], v01 * gi);
                    }
                    if (b1 >= 0) {
                        float gi = g_ginv[b1];
                        atomicAdd(&out[(size_t)b1 * DH + cn],     v10 * gi);
                        atomicAdd(&out[(size_t)b1 * DH + cn + 1], v11 * gi);
                    }
                }
            }
        }
    }
}

// ---------------- PDL launch helper (falls back to ordinary launch) ----------------
template <typename F, typename... Args>
static inline void pdl_launch(F f, dim3 grid, dim3 block, size_t smem, Args... args) {
    cudaLaunchConfig_t cfg = {};
    cfg.gridDim = grid;
    cfg.blockDim = block;
    cfg.dynamicSmemBytes = smem;
    cfg.stream = 0;
    cudaLaunchAttribute at[1];
    at[0].id = cudaLaunchAttributeProgrammaticStreamSerialization;
    at[0].val.programmaticStreamSerializationAllowed = 1;
    cfg.attrs = at;
    cfg.numAttrs = 1;
    if (cudaLaunchKernelEx(&cfg, f, args...) != cudaSuccess) {
        f<<<grid, block, smem>>>(args...);   // full stream ordering fallback
    }
}

// ---------------- launch ----------------
extern "C" void kernel_launch(void* const* d_in, const int* in_sizes, int n_in,
                              void* d_out, int out_size) {
    const float* x       = (const float*)d_in[0];
    const int*   ei      = (const int*)d_in[1];
    const int*   batch   = (const int*)d_in[2];
    const float* W1_rel  = (const float*)d_in[3];
    const float* W1_root = (const float*)d_in[4];
    const float* b1      = (const float*)d_in[5];
    const float* W2_rel  = (const float*)d_in[6];
    const float* W2_root = (const float*)d_in[7];
    const float* b2      = (const float*)d_in[8];
    float* out = (float*)d_out;

    const int N = in_sizes[0] / DIN;
    const int E = in_sizes[1] / 2;
    const int* src = ei;
    const int* dst = ei + E;

    const int SMEM = 3 * 10240 * (int)sizeof(__half);  // 61440 B
    cudaFuncSetAttribute(k_gemm<1>, cudaFuncAttributeMaxDynamicSharedMemorySize, SMEM);
    cudaFuncSetAttribute(k_gemm<2>, cudaFuncAttributeMaxDynamicSharedMemorySize, SMEM);
    cudaFuncSetAttribute(k_gemm<3>, cudaFuncAttributeMaxDynamicSharedMemorySize, SMEM);

    // zeroing via memset nodes (graph-capturable, not kernel launches)
    void *p_cnt = nullptr, *p_colsum = nullptr;
    cudaGetSymbolAddress(&p_cnt, g_cnt);
    cudaGetSymbolAddress(&p_colsum, g_colsum);
    cudaMemsetAsync(p_cnt, 0, (size_t)N * sizeof(int));
    cudaMemsetAsync(out, 0, (size_t)NG * DH * sizeof(float));
    cudaMemsetAsync(p_colsum, 0, DIN * sizeof(float));

    // fused front-end: histogram | weight prep | x prep
    const int HB = (E + 255) / 256;
    const int PB = (DH * 2 * DIN + DH * 2 * DH + 255) / 256;
    const int XB = 512;
    k_front<<<HB + PB + XB, 256>>>(dst, E, N, W1_rel, W1_root, W2_rel, W2_root, x,
                                   HB, PB, XB);

    // scan + handcrafted + graph counts; then CSR fill — PDL chained
    pdl_launch(k_mid, dim3(3), dim3(1024), 0, N, out, (const int*)batch);
    pdl_launch(k_fill, dim3((E + 255) / 256), dim3(256), 0, src, dst, E);

    dim3 ggrid((N + 127) / 128, 2);

    // layer 1: agg(x) -> gemm -> hA
    pdl_launch(k_agg16<DIN, 0>, dim3((N + 7) / 8), dim3(256), 0, N);
    pdl_launch(k_gemm<1>, ggrid, dim3(256), (size_t)SMEM,
               b1, N, (const int*)nullptr, (float*)nullptr);
    // layer 2: agg(hA) -> gemm -> hB
    pdl_launch(k_agg16<DH, 1>, dim3((N + 7) / 8), dim3(256), 0, N);
    pdl_launch(k_gemm<2>, ggrid, dim3(256), (size_t)SMEM,
               b2, N, (const int*)nullptr, (float*)nullptr);
    // layer 3: agg(hB) -> gemm -> fused mean-pool into out
    pdl_launch(k_agg16<DH, 2>, dim3((N + 7) / 8), dim3(256), 0, N);
    pdl_launch(k_gemm<3>, ggrid, dim3(256), (size_t)SMEM,
               b2, N, (const int*)batch, out);
}

// round 16
// speedup vs baseline: 1.0188x; 1.0188x over previous
#include <cuda_runtime.h>
#include <cuda_fp16.h>
#include <math.h>
#include <stdint.h>

#define NMAX 50000
#define EMAX 800000
#define DH   256
#define DIN  128
#define NG   64

// ---------------- device scratch ----------------
__device__ __half g_hA[(size_t)NMAX * DH];   // activations ping
__device__ __half g_hB[(size_t)NMAX * DH];   // activations pong
__device__ __half g_x16[(size_t)NMAX * DIN]; // x in fp16
__device__ __half g_agg16[(size_t)NMAX * DH];
// transposed weights fp16: Bt[n][k2], k2 = [rel | root]
__device__ __half g_Bt1[DH * 2 * DIN];
__device__ __half g_Bt2[DH * 2 * DH];

__device__ int   g_rowptr[NMAX + 1];
__device__ int   g_cnt [NMAX];
__device__ int   g_cnt2[NMAX];
__device__ int   g_col [EMAX];
__device__ float g_colsum[DIN];
__device__ float g_ginv[NG];    // 1 / max(graph count, 1)

// ---------------- helpers ----------------
#define MMA(c, a, b) \
    asm volatile("mma.sync.aligned.m16n8k16.row.col.f32.f16.f16.f32 " \
                 "{%0,%1,%2,%3},{%4,%5,%6,%7},{%8,%9},{%0,%1,%2,%3};" \
                 : "+f"((c)[0]), "+f"((c)[1]), "+f"((c)[2]), "+f"((c)[3]) \
                 : "r"((a)[0]), "r"((a)[1]), "r"((a)[2]), "r"((a)[3]), \
                   "r"((b)[0]), "r"((b)[1]))

__device__ __forceinline__ void ldsm4(unsigned* r, const __half* p) {
    unsigned a = (unsigned)__cvta_generic_to_shared((void*)p);
    asm volatile("ldmatrix.sync.aligned.m8n8.x4.shared.b16 {%0,%1,%2,%3}, [%4];"
                 : "=r"(r[0]), "=r"(r[1]), "=r"(r[2]), "=r"(r[3]) : "r"(a));
}
__device__ __forceinline__ void cpa16(__half* dst, const __half* src, bool pred) {
    unsigned d = (unsigned)__cvta_generic_to_shared((void*)dst);
    int sz = pred ? 16 : 0;
    asm volatile("cp.async.cg.shared.global [%0], [%1], 16, %2;"
                 :: "r"(d), "l"(src), "r"(sz));
}
#define CP_COMMIT() asm volatile("cp.async.commit_group;")

// PDL: signal dependents may launch / wait for predecessor grid completion.
__device__ __forceinline__ void gdc_launch() {
    asm volatile("griddepcontrol.launch_dependents;");
}
__device__ __forceinline__ void gdc_wait() {
    asm volatile("griddepcontrol.wait;" ::: "memory");
}

// ---------------- fused front-end: hist | weight prep | x prep ----------------
__global__ void k_front(const int* __restrict__ dst, int E, int n,
                        const float* __restrict__ W1_rel, const float* __restrict__ W1_root,
                        const float* __restrict__ W2_rel, const float* __restrict__ W2_root,
                        const float* __restrict__ x,
                        int HB, int PB, int XB) {
    gdc_launch();
    int bid = blockIdx.x;
    int t = threadIdx.x;
    if (bid < HB) {
        int e = bid * 256 + t;
        if (e < E) atomicAdd(&g_cnt[dst[e]], 1);
    } else if (bid < HB + PB) {
        int i = (bid - HB) * 256 + t;
        const int n1 = DH * 2 * DIN;
        const int n2 = DH * 2 * DH;
        if (i < n1) {
            int nn = i / (2 * DIN), k2 = i % (2 * DIN);
            float w = (k2 < DIN) ? W1_rel[(size_t)k2 * DH + nn]
                                 : W1_root[(size_t)(k2 - DIN) * DH + nn];
            g_Bt1[i] = __float2half_rn(w);
        } else if (i < n1 + n2) {
            int j = i - n1;
            int nn = j / (2 * DH), k2 = j % (2 * DH);
            float w = (k2 < DH) ? W2_rel[(size_t)k2 * DH + nn]
                                : W2_root[(size_t)(k2 - DH) * DH + nn];
            g_Bt2[j] = __float2half_rn(w);
        }
    } else {
        int xb = bid - HB - PB;
        int ch = t & 127;
        int half = t >> 7;
        float acc = 0.f;
        for (int r = xb * 2 + half; r < n; r += XB * 2) {
            float v = x[(size_t)r * DIN + ch];
            acc += v;
            g_x16[(size_t)r * DIN + ch] = __float2half_rn(v);
        }
        atomicAdd(&g_colsum[ch], acc);
    }
}

// ---------------- mid: scan (+cnt2 init) | handcrafted | graph counts ----------------
__global__ void k_mid(int n, float* __restrict__ out, const int* __restrict__ batch) {
    gdc_launch();
    gdc_wait();
    if (blockIdx.x == 0) {
        __shared__ int wsum[32];
        __shared__ int s_carry;
        int t = threadIdx.x, lane = t & 31, w = t >> 5;
        if (t == 0) s_carry = 0;
        __syncthreads();
        int ntile = (n + 1023) >> 10;
        for (int tile = 0; tile < ntile; ++tile) {
            int i = (tile << 10) + t;
            int v = (i < n) ? g_cnt[i] : 0;
            int x = v;
#pragma unroll
            for (int o = 1; o < 32; o <<= 1) {
                int y = __shfl_up_sync(0xFFFFFFFFu, x, o);
                if (lane >= o) x += y;
            }
            if (lane == 31) wsum[w] = x;
            __syncthreads();
            if (w == 0) {
                int s = wsum[lane];
#pragma unroll
                for (int o = 1; o < 32; o <<= 1) {
                    int y = __shfl_up_sync(0xFFFFFFFFu, s, o);
                    if (lane >= o) s += y;
                }
                wsum[lane] = s;
            }
            __syncthreads();
            int warpoff = (w == 0) ? 0 : wsum[w - 1];
            int excl = s_carry + warpoff + x - v;
            if (i < n) { g_rowptr[i] = excl; g_cnt2[i] = excl; }
            int tot = wsum[31];
            __syncthreads();
            if (t == 0) s_carry += tot;
            __syncthreads();
        }
        if (t == 0) g_rowptr[n] = s_carry;
    } else if (blockIdx.x == 1) {
        __shared__ float sh[DIN];
        int t = threadIdx.x;
        float v = (t < DIN) ? g_colsum[t] : 0.f;
        if (t < DIN) sh[t] = v;
        __syncthreads();
        for (int o = 64; o > 0; o >>= 1) {
            if (t < o) sh[t] += sh[t + o];
            __syncthreads();
        }
        float total = sh[0];
        if (t < DIN) out[NG * DH + t] = v / total;
        if (t == 0) out[NG * DH + DIN] = logf(total);
    } else {
        __shared__ int cnt[NG];
        int t = threadIdx.x;
        if (t < NG) cnt[t] = 0;
        __syncthreads();
        for (int i = t; i < n; i += 1024)
            atomicAdd(&cnt[batch[i]], 1);
        __syncthreads();
        if (t < NG) g_ginv[t] = 1.f / fmaxf((float)cnt[t], 1.f);
    }
}

// ---------------- fill: scatter src into CSR slots (cnt2 pre-set to rowptr) ----------------
__global__ void k_fill(const int* __restrict__ src,
                       const int* __restrict__ dst, int E) {
    gdc_launch();
    gdc_wait();
    int e = blockIdx.x * blockDim.x + threadIdx.x;
    if (e < E) {
        int d = dst[e];
        int pos = atomicAdd(&g_cnt2[d], 1);
        g_col[pos] = src[e];
    }
}

// ---------------- aggregation: warp per node, fp16 pairwise-tree accumulate ----------------
// Hybrid unroll (R15 post-mortem): D=128 uses 8-edge MLP=8 (measured -13%);
// D=256 keeps the 4-edge loop (8-edge uint4 buffering raised reg pressure and
// regressed). Both variants byte-identical to their measured-best forms.
// SRC: 0 = g_x16 (D=128), 1 = g_hA (D=256), 2 = g_hB (D=256)
template<int D, int SRC>
__global__ void k_agg16(int n) {
    gdc_launch();
    gdc_wait();
    const __half* __restrict__ h =
        (SRC == 0) ? g_x16 : (SRC == 1 ? (const __half*)g_hA : (const __half*)g_hB);
    int node = blockIdx.x * 8 + (threadIdx.x >> 5);
    int lane = threadIdx.x & 31;
    if (node >= n) return;
    int s = g_rowptr[node];
    int e = g_rowptr[node + 1];

    if (D == 256) {
        float acc[8] = {0, 0, 0, 0, 0, 0, 0, 0};
        int i = s;
#define PACC8(va, vb) { \
        float2 f0 = __half22float2(__hadd2(*(__half2*)&(va).x, *(__half2*)&(vb).x)); \
        float2 f1 = __half22float2(__hadd2(*(__half2*)&(va).y, *(__half2*)&(vb).y)); \
        float2 f2 = __half22float2(__hadd2(*(__half2*)&(va).z, *(__half2*)&(vb).z)); \
        float2 f3 = __half22float2(__hadd2(*(__half2*)&(va).w, *(__half2*)&(vb).w)); \
        acc[0] += f0.x; acc[1] += f0.y; acc[2] += f1.x; acc[3] += f1.y; \
        acc[4] += f2.x; acc[5] += f2.y; acc[6] += f3.x; acc[7] += f3.y; }
        for (; i + 4 <= e; i += 4) {
            int u0 = g_col[i], u1 = g_col[i + 1], u2 = g_col[i + 2], u3 = g_col[i + 3];
            uint4 v0 = ((const uint4*)(h + (size_t)u0 * D))[lane];
            uint4 v1 = ((const uint4*)(h + (size_t)u1 * D))[lane];
            uint4 v2 = ((const uint4*)(h + (size_t)u2 * D))[lane];
            uint4 v3 = ((const uint4*)(h + (size_t)u3 * D))[lane];
            PACC8(v0, v1) PACC8(v2, v3)
        }
        if (i + 2 <= e) {
            int u0 = g_col[i], u1 = g_col[i + 1];
            uint4 v0 = ((const uint4*)(h + (size_t)u0 * D))[lane];
            uint4 v1 = ((const uint4*)(h + (size_t)u1 * D))[lane];
            PACC8(v0, v1)
            i += 2;
        }
#undef PACC8
        if (i < e) {
            int u = g_col[i];
            uint4 v = ((const uint4*)(h + (size_t)u * D))[lane];
            float2 f0 = __half22float2(*(__half2*)&v.x);
            float2 f1 = __half22float2(*(__half2*)&v.y);
            float2 f2 = __half22float2(*(__half2*)&v.z);
            float2 f3 = __half22float2(*(__half2*)&v.w);
            acc[0] += f0.x; acc[1] += f0.y; acc[2] += f1.x; acc[3] += f1.y;
            acc[4] += f2.x; acc[5] += f2.y; acc[6] += f3.x; acc[7] += f3.y;
        }
        uint4 o;
        __half2 p0 = __floats2half2_rn(acc[0], acc[1]);
        __half2 p1 = __floats2half2_rn(acc[2], acc[3]);
        __half2 p2 = __floats2half2_rn(acc[4], acc[5]);
        __half2 p3 = __floats2half2_rn(acc[6], acc[7]);
        o.x = *(unsigned*)&p0; o.y = *(unsigned*)&p1;
        o.z = *(unsigned*)&p2; o.w = *(unsigned*)&p3;
        ((uint4*)(g_agg16 + (size_t)node * D))[lane] = o;
    } else {
        float acc[4] = {0, 0, 0, 0};
        int i = s;
#define PACC4(va, vb) { \
        float2 f0 = __half22float2(__hadd2(*(__half2*)&(va).x, *(__half2*)&(vb).x)); \
        float2 f1 = __half22float2(__hadd2(*(__half2*)&(va).y, *(__half2*)&(vb).y)); \
        acc[0] += f0.x; acc[1] += f0.y; acc[2] += f1.x; acc[3] += f1.y; }
        for (; i + 8 <= e; i += 8) {
            int u[8];
#pragma unroll
            for (int j = 0; j < 8; ++j) u[j] = g_col[i + j];
            uint2 v[8];
#pragma unroll
            for (int j = 0; j < 8; ++j)
                v[j] = ((const uint2*)(h + (size_t)u[j] * D))[lane];
            PACC4(v[0], v[1]) PACC4(v[2], v[3])
            PACC4(v[4], v[5]) PACC4(v[6], v[7])
        }
        if (i + 4 <= e) {
            int u0 = g_col[i], u1 = g_col[i + 1], u2 = g_col[i + 2], u3 = g_col[i + 3];
            uint2 v0 = ((const uint2*)(h + (size_t)u0 * D))[lane];
            uint2 v1 = ((const uint2*)(h + (size_t)u1 * D))[lane];
            uint2 v2 = ((const uint2*)(h + (size_t)u2 * D))[lane];
            uint2 v3 = ((const uint2*)(h + (size_t)u3 * D))[lane];
            PACC4(v0, v1) PACC4(v2, v3)
            i += 4;
        }
        if (i + 2 <= e) {
            int u0 = g_col[i], u1 = g_col[i + 1];
            uint2 v0 = ((const uint2*)(h + (size_t)u0 * D))[lane];
            uint2 v1 = ((const uint2*)(h + (size_t)u1 * D))[lane];
            PACC4(v0, v1)
            i += 2;
        }
#undef PACC4
        if (i < e) {
            int u = g_col[i];
            uint2 v = ((const uint2*)(h + (size_t)u * D))[lane];
            float2 f0 = __half22float2(*(__half2*)&v.x);
            float2 f1 = __half22float2(*(__half2*)&v.y);
            acc[0] += f0.x; acc[1] += f0.y; acc[2] += f1.x; acc[3] += f1.y;
        }
        uint2 o;
        __half2 p0 = __floats2half2_rn(acc[0], acc[1]);
        __half2 p1 = __floats2half2_rn(acc[2], acc[3]);
        o.x = *(unsigned*)&p0; o.y = *(unsigned*)&p1;
        ((uint2*)(g_agg16 + (size_t)node * D))[lane] = o;
    }
}

// ---------------- pipelined fp16 tensor-core GEMM ----------------
// h_out = relu([agg16 | root] @ Bt^T + bias), single-product fp16, f32 accum.
// BM=128, BN=128, BK=32, 256 threads, warps 4Mx2N (warp tile 32x64).
// PDL: B-weight prefetch of stages 0/1 issued BEFORE griddepcontrol.wait.
// LAYER 3: no global h write; mean-pool fused into epilogue.
template<int LAYER>
__global__ void __launch_bounds__(256, 2)
k_gemm(const float* __restrict__ bias, int M,
       const int* __restrict__ batch, float* __restrict__ out) {
    constexpr int K  = (LAYER == 1) ? DIN : DH;
    constexpr int K2 = 2 * K;
    constexpr int T  = K2 / 32;
    constexpr bool POOL = (LAYER == 3);

    const __half* __restrict__ root =
        (LAYER == 1) ? g_x16 : (LAYER == 2 ? (const __half*)g_hA : (const __half*)g_hB);
    const __half* __restrict__ Bt = (LAYER == 1) ? g_Bt1 : g_Bt2;
    __half* __restrict__ hout = (LAYER == 2) ? g_hB : g_hA;

    extern __shared__ __half sm[];
    __shared__ float sbias[DH];
    __shared__ int s_batch[128];

    const int tid  = threadIdx.x;
    const int lane = tid & 31;
    const int warp = tid >> 5;
    const int wm   = warp >> 1;
    const int wn   = warp & 1;
    const int gID  = lane >> 2;
    const int tg   = lane & 3;
    const int m0   = blockIdx.x * 128;
    const int n0   = blockIdx.y * 128;

    gdc_launch();

    // ---- independent-of-predecessor prefetch (inputs only) ----
    if (tid < DH) sbias[tid] = bias[tid];
    if (POOL && tid < 128) {
        int r = m0 + tid;
        s_batch[tid] = (r < M) ? batch[r] : -1;
    }

    auto loadB = [&](int it, int s) {
        __half* st = sm + s * 10240;
#pragma unroll
        for (int i = 0; i < 2; ++i) {
            int q = tid + 256 * i;
            int r = q >> 2, cq = q & 3;
            cpa16(st + 5120 + r * 40 + cq * 8,
                  Bt + (size_t)(n0 + r) * K2 + it * 32 + cq * 8, true);
        }
    };
    auto loadA = [&](int it, int s) {
        const bool first = (it * 32 < K);
        const __half* __restrict__ srcA = first ? g_agg16 : root;
        const int col = first ? it * 32 : it * 32 - K;
        __half* st = sm + s * 10240;
#pragma unroll
        for (int i = 0; i < 2; ++i) {
            int q = tid + 256 * i;
            int r = q >> 2, cq = q & 3;
            int gr = m0 + r;
            bool p = gr < M;
            cpa16(st + r * 40 + cq * 8,
                  srcA + (size_t)(p ? gr : 0) * K + col + cq * 8, p);
        }
    };

    loadB(0, 0);
    loadB(1, 1);

    gdc_wait();   // predecessor (agg) complete; A data now valid

    loadA(0, 0);
    CP_COMMIT();   // G0 = {B0, B1, A0}
    loadA(1, 1);
    CP_COMMIT();   // G1 = {A1}

    float c[2][8][4];
#pragma unroll
    for (int mt = 0; mt < 2; ++mt)
#pragma unroll
        for (int nt = 0; nt < 8; ++nt)
#pragma unroll
            for (int q = 0; q < 4; ++q) c[mt][nt][q] = 0.f;

    const int lrow = lane & 15;
    const int lk   = (lane >> 4) * 8;

    for (int it = 0; it < T; ++it) {
        int s = it % 3;
        if (it + 1 < T) asm volatile("cp.async.wait_group 1;");
        else            asm volatile("cp.async.wait_group 0;");
        __syncthreads();
        if (it + 2 < T) { loadA(it + 2, (it + 2) % 3); loadB(it + 2, (it + 2) % 3); }
        CP_COMMIT();

        __half* st = sm + s * 10240;
#pragma unroll
        for (int ks = 0; ks < 32; ks += 16) {
            unsigned a[2][4], b[8][2];
#pragma unroll
            for (int mt = 0; mt < 2; ++mt) {
                int rr = wm * 32 + mt * 16 + lrow;
                ldsm4(a[mt], st + rr * 40 + ks + lk);
            }
#pragma unroll
            for (int nh = 0; nh < 4; ++nh) {
                int nn = wn * 64 + nh * 16 + lrow;
                unsigned r4[4];
                ldsm4(r4, st + 5120 + nn * 40 + ks + lk);
                b[nh * 2][0] = r4[0]; b[nh * 2 + 1][0] = r4[1];
                b[nh * 2][1] = r4[2]; b[nh * 2 + 1][1] = r4[3];
            }
#pragma unroll
            for (int mt = 0; mt < 2; ++mt)
#pragma unroll
                for (int nt = 0; nt < 8; ++nt)
                    MMA(c[mt][nt], a[mt], b[nt]);
        }
    }

    if (!POOL) {
#pragma unroll
        for (int nt = 0; nt < 8; ++nt) {
            int cn = n0 + wn * 64 + nt * 8 + tg * 2;
            float bx = sbias[cn];
            float by = sbias[cn + 1];
#pragma unroll
            for (int mt = 0; mt < 2; ++mt) {
                int r0 = m0 + wm * 32 + mt * 16 + gID;
                int r1 = r0 + 8;
                if (r0 < M) {
                    __half2 o = __floats2half2_rn(fmaxf(c[mt][nt][0] + bx, 0.f),
                                                  fmaxf(c[mt][nt][1] + by, 0.f));
                    *(__half2*)(hout + (size_t)r0 * DH + cn) = o;
                }
                if (r1 < M) {
                    __half2 o = __floats2half2_rn(fmaxf(c[mt][nt][2] + bx, 0.f),
                                                  fmaxf(c[mt][nt][3] + by, 0.f));
                    *(__half2*)(hout + (size_t)r1 * DH + cn) = o;
                }
            }
        }
    } else {
        // bias + relu + fused mean-pool (no global h write)
#pragma unroll
        for (int nt = 0; nt < 8; ++nt) {
            int cn = n0 + wn * 64 + nt * 8 + tg * 2;
            float bx = sbias[cn];
            float by = sbias[cn + 1];
#pragma unroll
            for (int mt = 0; mt < 2; ++mt) {
                int base = wm * 32 + mt * 16;
                int b0 = s_batch[base + gID];
                int b1 = s_batch[base + gID + 8];
                float v00 = fmaxf(c[mt][nt][0] + bx, 0.f);
                float v01 = fmaxf(c[mt][nt][1] + by, 0.f);
                float v10 = fmaxf(c[mt][nt][2] + bx, 0.f);
                float v11 = fmaxf(c[mt][nt][3] + by, 0.f);
                if (b0 < 0) { v00 = 0.f; v01 = 0.f; }
                if (b1 < 0) { v10 = 0.f; v11 = 0.f; }
                int bf = s_batch[base];
                int bl = s_batch[base + 15];
                if (bf == bl) {
                    float s0 = v00 + v10;
                    float s1 = v01 + v11;
                    s0 += __shfl_down_sync(0xFFFFFFFFu, s0, 16);
                    s1 += __shfl_down_sync(0xFFFFFFFFu, s1, 16);
                    s0 += __shfl_down_sync(0xFFFFFFFFu, s0, 8);
                    s1 += __shfl_down_sync(0xFFFFFFFFu, s1, 8);
                    s0 += __shfl_down_sync(0xFFFFFFFFu, s0, 4);
                    s1 += __shfl_down_sync(0xFFFFFFFFu, s1, 4);
                    if (gID == 0 && bf >= 0) {
                        float gi = g_ginv[bf];
                        atomicAdd(&out[(size_t)bf * DH + cn],     s0 * gi);
                        atomicAdd(&out[(size_t)bf * DH + cn + 1], s1 * gi);
                    }
                } else {
                    if (b0 >= 0) {
                        float gi = g_ginv[b0];
                        atomicAdd(&out[(size_t)b0 * DH + cn],     v00 * gi);
                        atomicAdd(&out[(size_t)b0 * DH + cn + 1], v01 * gi);
                    }
                    if (b1 >= 0) {
                        float gi = g_ginv[b1];
                        atomicAdd(&out[(size_t)b1 * DH + cn],     v10 * gi);
                        atomicAdd(&out[(size_t)b1 * DH + cn + 1], v11 * gi);
                    }
                }
            }
        }
    }
}

// ---------------- PDL launch helper (falls back to ordinary launch) ----------------
template <typename F, typename... Args>
static inline void pdl_launch(F f, dim3 grid, dim3 block, size_t smem, Args... args) {
    cudaLaunchConfig_t cfg = {};
    cfg.gridDim = grid;
    cfg.blockDim = block;
    cfg.dynamicSmemBytes = smem;
    cfg.stream = 0;
    cudaLaunchAttribute at[1];
    at[0].id = cudaLaunchAttributeProgrammaticStreamSerialization;
    at[0].val.programmaticStreamSerializationAllowed = 1;
    cfg.attrs = at;
    cfg.numAttrs = 1;
    if (cudaLaunchKernelEx(&cfg, f, args...) != cudaSuccess) {
        f<<<grid, block, smem>>>(args...);   // full stream ordering fallback
    }
}

// ---------------- launch ----------------
extern "C" void kernel_launch(void* const* d_in, const int* in_sizes, int n_in,
                              void* d_out, int out_size) {
    const float* x       = (const float*)d_in[0];
    const int*   ei      = (const int*)d_in[1];
    const int*   batch   = (const int*)d_in[2];
    const float* W1_rel  = (const float*)d_in[3];
    const float* W1_root = (const float*)d_in[4];
    const float* b1      = (const float*)d_in[5];
    const float* W2_rel  = (const float*)d_in[6];
    const float* W2_root = (const float*)d_in[7];
    const float* b2      = (const float*)d_in[8];
    float* out = (float*)d_out;

    const int N = in_sizes[0] / DIN;
    const int E = in_sizes[1] / 2;
    const int* src = ei;
    const int* dst = ei + E;

    const int SMEM = 3 * 10240 * (int)sizeof(__half);  // 61440 B
    cudaFuncSetAttribute(k_gemm<1>, cudaFuncAttributeMaxDynamicSharedMemorySize, SMEM);
    cudaFuncSetAttribute(k_gemm<2>, cudaFuncAttributeMaxDynamicSharedMemorySize, SMEM);
    cudaFuncSetAttribute(k_gemm<3>, cudaFuncAttributeMaxDynamicSharedMemorySize, SMEM);

    // zeroing via memset nodes (graph-capturable, not kernel launches)
    void *p_cnt = nullptr, *p_colsum = nullptr;
    cudaGetSymbolAddress(&p_cnt, g_cnt);
    cudaGetSymbolAddress(&p_colsum, g_colsum);
    cudaMemsetAsync(p_cnt, 0, (size_t)N * sizeof(int));
    cudaMemsetAsync(out, 0, (size_t)NG * DH * sizeof(float));
    cudaMemsetAsync(p_colsum, 0, DIN * sizeof(float));

    // fused front-end: histogram | weight prep | x prep
    const int HB = (E + 255) / 256;
    const int PB = (DH * 2 * DIN + DH * 2 * DH + 255) / 256;
    const int XB = 512;
    k_front<<<HB + PB + XB, 256>>>(dst, E, N, W1_rel, W1_root, W2_rel, W2_root, x,
                                   HB, PB, XB);

    // scan + handcrafted + graph counts; then CSR fill — PDL chained
    pdl_launch(k_mid, dim3(3), dim3(1024), 0, N, out, (const int*)batch);
    pdl_launch(k_fill, dim3((E + 255) / 256), dim3(256), 0, src, dst, E);

    dim3 ggrid((N + 127) / 128, 2);

    // layer 1: agg(x) -> gemm -> hA
    pdl_launch(k_agg16<DIN, 0>, dim3((N + 7) / 8), dim3(256), 0, N);
    pdl_launch(k_gemm<1>, ggrid, dim3(256), (size_t)SMEM,
               b1, N, (const int*)nullptr, (float*)nullptr);
    // layer 2: agg(hA) -> gemm -> hB
    pdl_launch(k_agg16<DH, 1>, dim3((N + 7) / 8), dim3(256), 0, N);
    pdl_launch(k_gemm<2>, ggrid, dim3(256), (size_t)SMEM,
               b2, N, (const int*)nullptr, (float*)nullptr);
    // layer 3: agg(hB) -> gemm -> fused mean-pool into out
    pdl_launch(k_agg16<DH, 2>, dim3((N + 7) / 8), dim3(256), 0, N);
    pdl_launch(k_gemm<3>, ggrid, dim3(256), (size_t)SMEM,
               b2, N, (const int*)batch, out);
}